// round 13
// baseline (speedup 1.0000x reference)
#include <cuda_runtime.h>
#include <cuda_bf16.h>
#include <cstdint>

#define BB 2
#define CIN 128
#define COUT 64
#define KK 64
#define HWD 16384          // 128*128
#define NPIX (BB*HWD)      // 32768
#define GPX 32             // pixels per gemm block
#define NGB (NPIX/GPX)     // 1024 gemm blocks

// ---------------- scratch (device globals; no allocation) ----------------
__device__ float g_xt[BB*COUT*HWD];        // xt in [b][o][p] layout (8MB)
__device__ float g_sumsp[BB*KK*COUT*2];    // partial bin sums [b][k][o][z]
__device__ float g_cntp[BB*KK*2];          // partial counts   [b][k][z]
__device__ float g_A[COUT*COUT];           // inv(cov)
__device__ float g_adjmT[BB*KK*COUT];      // adj @ means, TRANSPOSED [b][o][i]
__device__ float g_psum[16*COUT];          // BN partial sums  [(b*8+cx)][o]
__device__ float g_psq[16*COUT];           // BN partial sumsq

// macro params named to avoid .x/.y/.z/.w member-token capture
#define FMA4(ACC_, XS_, WV_) { (ACC_).x += (XS_)*(WV_).x; (ACC_).y += (XS_)*(WV_).y; (ACC_).z += (XS_)*(WV_).z; (ACC_).w += (XS_)*(WV_).w; }

// ---------------- GEMM xt = x*Wft (block>0) + GJ inverse with staged loads (block 0) ----------------
__global__ void __launch_bounds__(128) k_gemm(const float* __restrict__ x,
                                              const float* __restrict__ Wft,
                                              const float* __restrict__ Wm) {
    __shared__ __align__(16) float sbuf[8192];   // gemm: W as float4[2048] (32KB); inv: 64*65 aug
    __shared__ float sdiag[64];
    const int tid = threadIdx.x;

    if (blockIdx.x == 0) {
        // ======== packed-slot Gauss-Jordan inverse of cov = Wm Wm^T (SPD, no pivot) ========
        for (int i = tid; i < 64*64; i += 128) sbuf[(i >> 6)*65 + (i & 63)] = Wm[i];
        __syncthreads();
        // cov via 4x8 register tile (16x8 thread grid)
        const int ti = tid & 15;
        const int tj = tid >> 4;
        float acc[4][8];
        #pragma unroll
        for (int p = 0; p < 4; p++)
            #pragma unroll
            for (int q = 0; q < 8; q++) acc[p][q] = 0.f;
        for (int c = 0; c < 64; c++) {
            float ai[4], bj[8];
            #pragma unroll
            for (int p = 0; p < 4; p++) ai[p] = sbuf[(ti*4 + p)*65 + c];
            #pragma unroll
            for (int q = 0; q < 8; q++) bj[q] = sbuf[(tj*8 + q)*65 + c];
            #pragma unroll
            for (int p = 0; p < 4; p++)
                #pragma unroll
                for (int q = 0; q < 8; q++) acc[p][q] += ai[p] * bj[q];
        }
        __syncthreads();
        #pragma unroll
        for (int p = 0; p < 4; p++)
            #pragma unroll
            for (int q = 0; q < 8; q++) sbuf[(ti*4 + p)*65 + tj*8 + q] = acc[p][q];

        // packed unnormalized elimination, aliasing broken by batch load -> compute -> store
        const int r = tid & 63;
        const int part = tid >> 6;      // 2 parts x 32 slots
        const int j0 = part*32;
        float* myrow = sbuf + r*65;
        for (int c = 0; c < 64; c++) {
            __syncthreads();
            if (r == c) {
                if (part == 0) sdiag[c] = myrow[c];
                continue;
            }
            const float* prow = sbuf + c*65;
            float pv[32], mv[32];
            #pragma unroll
            for (int j = 0; j < 32; j++) pv[j] = prow[j0 + j];
            #pragma unroll
            for (int j = 0; j < 32; j++) mv[j] = myrow[j0 + j];
            float d = prow[c];
            float f = __fdividef(myrow[c], d);
            #pragma unroll
            for (int j = 0; j < 32; j++) {
                int jj = j0 + j;
                float base = mv[j];
                if (r == c - 1 && jj == r) base = 1.0f;   // deferred pivot-diag identity
                float val = base - f * pv[j];
                if (jj == c) val = -f;                    // newborn right-col-c entry
                myrow[jj] = val;
            }
        }
        __syncthreads();
        for (int t = tid; t < 64*64; t += 128) {
            int rr = t >> 6, cc = t & 63;
            float v = sbuf[rr*65 + cc];
            if (rr == 63 && cc == 63) v = 1.0f;           // last pivot identity never materialized
            g_A[t] = __fdividef(v, sdiag[rr]);
        }
        return;
    }

    // ======== GEMM: 32 px x 64 outs; thread tile 4px x 4out; register-pipelined direct LDG ========
    float4* sW4 = reinterpret_cast<float4*>(sbuf);          // [128c][16 f4]
    const int GP = (blockIdx.x - 1) * GPX;
    const int b  = GP >> 14;
    const int P0 = GP & (HWD - 1);
    const int quad = tid & 7;         // pixel quad: px = quad*4..+3 (8 quads = 32 px)
    const int og   = tid >> 3;        // out group: o = og*4..+3 (16 groups = 64 outs)

    #pragma unroll
    for (int t = 0; t < 16; t++)
        sW4[tid + t*128] = __ldg(reinterpret_cast<const float4*>(Wft) + tid + t*128);
    __syncthreads();

    float4 a0 = make_float4(0.f,0.f,0.f,0.f), a1 = a0, a2 = a0, a3 = a0;   // px0..3 x outs og*4..+3

    const float* xb = x + (size_t)b * CIN * HWD + P0 + quad*4;
    const float4* sWp = sW4 + og;

    float4 L[4];
    #pragma unroll
    for (int i = 0; i < 4; i++)
        L[i] = *reinterpret_cast<const float4*>(xb + (size_t)i * HWD);

    for (int cb = 0; cb < CIN; cb += 4) {
        float4 M[4];
        if (cb + 4 < CIN) {
            #pragma unroll
            for (int i = 0; i < 4; i++)
                M[i] = *reinterpret_cast<const float4*>(xb + (size_t)(cb + 4 + i) * HWD);
        }
        #pragma unroll
        for (int i = 0; i < 4; i++) {
            float4 wv = sWp[(cb + i)*16];
            FMA4(a0, L[i].x, wv);
            FMA4(a1, L[i].y, wv);
            FMA4(a2, L[i].z, wv);
            FMA4(a3, L[i].w, wv);
        }
        #pragma unroll
        for (int i = 0; i < 4; i++) L[i] = M[i];
    }

    float* xtb = g_xt + (size_t)b * COUT * HWD + P0 + quad*4;
    const int ob = og*4;
    *reinterpret_cast<float4*>(xtb + (size_t)(ob+0) * HWD) = make_float4(a0.x, a1.x, a2.x, a3.x);
    *reinterpret_cast<float4*>(xtb + (size_t)(ob+1) * HWD) = make_float4(a0.y, a1.y, a2.y, a3.y);
    *reinterpret_cast<float4*>(xtb + (size_t)(ob+2) * HWD) = make_float4(a0.z, a1.z, a2.z, a3.z);
    *reinterpret_cast<float4*>(xtb + (size_t)(ob+3) * HWD) = make_float4(a0.w, a1.w, a2.w, a3.w);
}

// ---------------- kernel: per-bin partial sums + counts via shared atomics ----------------
__global__ void __launch_bounds__(256) k_sums(const int* __restrict__ idx) {
    __shared__ float sbm[64*33];
    const int tid = threadIdx.x;
    const int o = blockIdx.x, b = blockIdx.y, z = blockIdx.z;
    for (int i = tid; i < 64*33; i += 256) sbm[i] = 0.f;
    __syncthreads();
    const int col = tid & 31;
    const int4* ip4 = reinterpret_cast<const int4*>(idx + b*HWD);
    const int q0 = z*2048;
    if (o < COUT) {
        const float4* xt4 = reinterpret_cast<const float4*>(g_xt + (size_t)(b*COUT + o) * HWD);
        #pragma unroll
        for (int it = 0; it < 8; it++) {
            int q = q0 + it*256 + tid;
            float4 v = __ldg(xt4 + q);
            int4 kk = __ldg(ip4 + q);
            atomicAdd(&sbm[kk.x*33 + col], v.x);
            atomicAdd(&sbm[kk.y*33 + col], v.y);
            atomicAdd(&sbm[kk.z*33 + col], v.z);
            atomicAdd(&sbm[kk.w*33 + col], v.w);
        }
    } else {
        #pragma unroll
        for (int it = 0; it < 8; it++) {
            int q = q0 + it*256 + tid;
            int4 kk = __ldg(ip4 + q);
            atomicAdd(&sbm[kk.x*33 + col], 1.f);
            atomicAdd(&sbm[kk.y*33 + col], 1.f);
            atomicAdd(&sbm[kk.z*33 + col], 1.f);
            atomicAdd(&sbm[kk.w*33 + col], 1.f);
        }
    }
    __syncthreads();
    if (tid < 128) {
        int k = tid >> 1, h = tid & 1;
        float s = 0.f;
        const float* row = sbm + k*33 + h*16;
        #pragma unroll
        for (int m = 0; m < 16; m++) s += row[m];
        s += __shfl_xor_sync(0xffffffffu, s, 1);
        if (h == 0) {
            if (o < COUT) g_sumsp[((b*64 + k)*64 + o)*2 + z] = s;
            else          g_cntp[(b*64 + k)*2 + z] = s;
        }
    }
}

// ---------------- kernel: adjacency + adj@means per (b,i) ----------------
__global__ void __launch_bounds__(256) k_adj() {
    __shared__ float sMe[64*65];
    __shared__ float sA[64*64];
    __shared__ float adjrow[64];
    __shared__ float red[256];
    const int tid = threadIdx.x;
    const int b = blockIdx.x >> 6;
    const int i = blockIdx.x & 63;

    for (int t = tid; t < 64*64; t += 256) {
        int k = t >> 6, o = t & 63;
        float2 sp = *reinterpret_cast<const float2*>(g_sumsp + ((size_t)b*4096 + t)*2);
        float sum = sp.x + sp.y;
        float2 cp = *reinterpret_cast<const float2*>(g_cntp + (b*64 + k)*2);
        float cnt = cp.x + cp.y;
        float den = cnt + (cnt == 0.f ? 1.f : 0.f);
        sMe[k*65 + o] = sum / den;
        sA[t] = g_A[t];
    }
    __syncthreads();

    const int j = tid & 63, s = tid >> 6;
    float dreg[64];
    #pragma unroll
    for (int d = 0; d < 64; d++) dreg[d] = sMe[i*65 + d] - sMe[j*65 + d];
    float q = 0.f;
    for (int c = s*16; c < s*16 + 16; c++) {
        float w = 0.f;
        const float4* ar = reinterpret_cast<const float4*>(sA + c*64);
        #pragma unroll
        for (int d4 = 0; d4 < 16; d4++) {
            float4 aa = ar[d4];
            w += aa.x*dreg[4*d4] + aa.y*dreg[4*d4+1] + aa.z*dreg[4*d4+2] + aa.w*dreg[4*d4+3];
        }
        q += dreg[c] * w;
    }
    red[tid] = q;
    __syncthreads();
    if (tid < 64) {
        float qt = red[tid] + red[64 + tid] + red[128 + tid] + red[192 + tid];
        float dist = (tid == i) ? 1e-6f : sqrtf(fmaxf(qt, 1e-12f));
        adjrow[tid] = expf(-dist);
    }
    __syncthreads();
    const int o = tid & 63;
    float part = 0.f;
    for (int jj = s*16; jj < s*16 + 16; jj++) part += adjrow[jj] * sMe[jj*65 + o];
    red[tid] = part;
    __syncthreads();
    if (tid < 64)
        g_adjmT[b*4096 + tid*64 + i] = red[tid] + red[64 + tid] + red[128 + tid] + red[192 + tid];
}

// ---------------- kernel: BN partial statistics ----------------
__global__ void __launch_bounds__(256) k_stats(const int* __restrict__ idx) {
    __shared__ float sAm[64];
    const int tid = threadIdx.x;
    const int cx = blockIdx.x, o = blockIdx.y, b = blockIdx.z;
    if (tid < 64) sAm[tid] = g_adjmT[b*4096 + o*64 + tid];
    __syncthreads();
    const float4* xt4 = reinterpret_cast<const float4*>(g_xt + (size_t)(b*COUT + o) * HWD);
    const int4*   ip4 = reinterpret_cast<const int4*>(idx + b*HWD);
    int q0 = cx * 512 + tid;
    float s = 0.f, sq = 0.f;
    #pragma unroll
    for (int it = 0; it < 2; it++) {
        int q = q0 + it*256;
        float4 v = __ldg(xt4 + q);
        int4 kk = __ldg(ip4 + q);
        float f0 = fmaxf(v.x + sAm[kk.x], 0.f);
        float f1 = fmaxf(v.y + sAm[kk.y], 0.f);
        float f2 = fmaxf(v.z + sAm[kk.z], 0.f);
        float f3 = fmaxf(v.w + sAm[kk.w], 0.f);
        s  += f0 + f1 + f2 + f3;
        sq += f0*f0 + f1*f1 + f2*f2 + f3*f3;
    }
    #pragma unroll
    for (int off = 16; off; off >>= 1) {
        s  += __shfl_down_sync(0xffffffffu, s, off);
        sq += __shfl_down_sync(0xffffffffu, sq, off);
    }
    __shared__ float rs[8], rq[8];
    if ((tid & 31) == 0) { rs[tid >> 5] = s; rq[tid >> 5] = sq; }
    __syncthreads();
    if (tid == 0) {
        float S = 0.f, Q = 0.f;
        #pragma unroll
        for (int w = 0; w < 8; w++) { S += rs[w]; Q += rq[w]; }
        g_psum[(b*8 + cx)*COUT + o] = S;
        g_psq [(b*8 + cx)*COUT + o] = Q;
    }
}

// ---------------- kernel: normalize + write output ----------------
__global__ void __launch_bounds__(256) k_out(const int* __restrict__ idx,
                                             const float* __restrict__ gamma,
                                             const float* __restrict__ beta,
                                             float* __restrict__ out) {
    __shared__ float sAm[64];
    __shared__ float sc, shf;
    const int tid = threadIdx.x;
    const int cx = blockIdx.x, o = blockIdx.y, b = blockIdx.z;
    if (tid < 64) sAm[tid] = g_adjmT[b*4096 + o*64 + tid];
    if (tid == 0) {
        float S = 0.f, Q = 0.f;
        #pragma unroll
        for (int i = 0; i < 16; i++) { S += g_psum[i*COUT + o]; Q += g_psq[i*COUT + o]; }
        const float invN = 1.0f / (float)NPIX;
        float mean = S * invN;
        float var  = Q * invN - mean * mean;
        float inv  = 1.0f / sqrtf(var + 1e-5f);
        float g = __ldg(gamma + o), be = __ldg(beta + o);
        sc  = g * inv;
        shf = be - mean * g * inv;
    }
    __syncthreads();
    const float4* xt4 = reinterpret_cast<const float4*>(g_xt + (size_t)(b*COUT + o) * HWD);
    const int4*   ip4 = reinterpret_cast<const int4*>(idx + b*HWD);
    float4* o4 = reinterpret_cast<float4*>(out + (size_t)(b*COUT + o) * HWD);
    int q0 = cx * 512 + tid;
    float lsc = sc, lsh = shf;
    #pragma unroll
    for (int it = 0; it < 2; it++) {
        int q = q0 + it*256;
        float4 v = __ldg(xt4 + q);
        int4 kk = __ldg(ip4 + q);
        float4 r;
        r.x = fmaxf(v.x + sAm[kk.x], 0.f) * lsc + lsh;
        r.y = fmaxf(v.y + sAm[kk.y], 0.f) * lsc + lsh;
        r.z = fmaxf(v.z + sAm[kk.z], 0.f) * lsc + lsh;
        r.w = fmaxf(v.w + sAm[kk.w], 0.f) * lsc + lsh;
        o4[q] = r;
    }
}

// ---------------- launch ----------------
extern "C" void kernel_launch(void* const* d_in, const int* in_sizes, int n_in,
                              void* d_out, int out_size) {
    const float* x     = (const float*)d_in[0];
    const int*   idx   = (const int*)  d_in[1];
    const float* Wft   = (const float*)d_in[2];
    const float* Wm    = (const float*)d_in[3];
    const float* gamma = (const float*)d_in[4];
    const float* beta  = (const float*)d_in[5];
    float* out = (float*)d_out;

    k_gemm<<<NGB + 1, 128>>>(x, Wft, Wm);
    k_sums<<<dim3(COUT + 1, BB, 2), 256>>>(idx);
    k_adj<<<BB*KK, 256>>>();
    k_stats<<<dim3(8, COUT, BB), 256>>>(idx);
    k_out<<<dim3(8, COUT, BB), 256>>>(idx, gamma, beta, out);
}

// round 14
// speedup vs baseline: 1.0547x; 1.0547x over previous
#include <cuda_runtime.h>
#include <cuda_bf16.h>
#include <cstdint>

#define BB 2
#define CIN 128
#define COUT 64
#define KK 64
#define HWD 16384          // 128*128
#define NPIX (BB*HWD)      // 32768
#define GPX 64             // pixels per gemm block
#define NGB (NPIX/GPX)     // 512 gemm blocks

// ---------------- scratch (device globals; no allocation) ----------------
__device__ float g_xt[BB*COUT*HWD];        // xt in [b][o][p] layout (8MB)
__device__ float g_sumsp[BB*KK*COUT*2];    // partial bin sums [b][k][o][z]
__device__ float g_cntp[BB*KK*2];          // partial counts   [b][k][z]
__device__ float g_A[COUT*COUT];           // inv(cov)
__device__ float g_adjmT[BB*KK*COUT];      // adj @ means, TRANSPOSED [b][o][i]
__device__ float g_psum[16*COUT];          // BN partial sums  [(b*8+cx)][o]
__device__ float g_psq[16*COUT];           // BN partial sumsq

// macro params named to avoid .x/.y/.z/.w member-token capture
#define FMA4(ACC_, XS_, WV_) { (ACC_).x += (XS_)*(WV_).x; (ACC_).y += (XS_)*(WV_).y; (ACC_).z += (XS_)*(WV_).z; (ACC_).w += (XS_)*(WV_).w; }

// ---------------- GEMM xt = x*Wft (block>0, 256 thr) + GJ inverse (block 0, 256 thr) ----------------
__global__ void __launch_bounds__(256) k_gemm(const float* __restrict__ x,
                                              const float* __restrict__ Wft,
                                              const float* __restrict__ Wm) {
    __shared__ __align__(16) float sbuf[8192];   // gemm: W float4[2048] (32KB); inv: 64*65 aug
    __shared__ float sdiag[64];
    const int tid = threadIdx.x;

    if (blockIdx.x == 0) {
        // ======== packed-slot Gauss-Jordan inverse of cov = Wm Wm^T (SPD, no pivot) ========
        for (int i = tid; i < 64*64; i += 256) sbuf[(i >> 6)*65 + (i & 63)] = Wm[i];
        __syncthreads();
        // cov via 4x4 register tile (16x16 thread grid)
        const int ti = tid & 15;
        const int tj = tid >> 4;
        float acc[4][4];
        #pragma unroll
        for (int p = 0; p < 4; p++)
            #pragma unroll
            for (int q = 0; q < 4; q++) acc[p][q] = 0.f;
        for (int c = 0; c < 64; c++) {
            float ai[4], bj[4];
            #pragma unroll
            for (int p = 0; p < 4; p++) ai[p] = sbuf[(ti*4 + p)*65 + c];
            #pragma unroll
            for (int q = 0; q < 4; q++) bj[q] = sbuf[(tj*4 + q)*65 + c];
            #pragma unroll
            for (int p = 0; p < 4; p++)
                #pragma unroll
                for (int q = 0; q < 4; q++) acc[p][q] += ai[p] * bj[q];
        }
        __syncthreads();
        #pragma unroll
        for (int p = 0; p < 4; p++)
            #pragma unroll
            for (int q = 0; q < 4; q++) sbuf[(ti*4 + p)*65 + tj*4 + q] = acc[p][q];

        // packed unnormalized elimination; batch-load(16) -> compute -> batch-store; 1 barrier/iter
        const int r = tid & 63;
        const int part = tid >> 6;      // 4 parts x 16 slots
        const int j0 = part*16;
        float* myrow = sbuf + r*65;
        for (int c = 0; c < 64; c++) {
            __syncthreads();
            if (r == c) {
                if (part == 0) sdiag[c] = myrow[c];
                continue;
            }
            const float* prow = sbuf + c*65;
            float pv[16], mv[16];
            #pragma unroll
            for (int j = 0; j < 16; j++) pv[j] = prow[j0 + j];
            #pragma unroll
            for (int j = 0; j < 16; j++) mv[j] = myrow[j0 + j];
            float d = prow[c];
            float f = __fdividef(myrow[c], d);
            #pragma unroll
            for (int j = 0; j < 16; j++) {
                int jj = j0 + j;
                float base = mv[j];
                if (r == c - 1 && jj == r) base = 1.0f;   // deferred pivot-diag identity
                float val = base - f * pv[j];
                if (jj == c) val = -f;                    // newborn right-col-c entry
                myrow[jj] = val;
            }
        }
        __syncthreads();
        for (int t = tid; t < 64*64; t += 256) {
            int rr = t >> 6, cc = t & 63;
            float v = sbuf[rr*65 + cc];
            if (rr == 63 && cc == 63) v = 1.0f;           // last pivot identity never materialized
            g_A[t] = __fdividef(v, sdiag[rr]);
        }
        return;
    }

    // ======== GEMM: 64 px x 64 outs; 256 thr; thread tile 4px x 4out; register-pipelined LDG ========
    float4* sW4 = reinterpret_cast<float4*>(sbuf);          // [128c][16 f4]
    const int GP = (blockIdx.x - 1) * GPX;
    const int b  = GP >> 14;
    const int P0 = GP & (HWD - 1);
    const int quad = tid & 15;        // pixel quad: px = quad*4..+3 (16 quads = 64 px)
    const int og   = tid >> 4;        // out group: o = og*4..+3 (16 groups = 64 outs)

    #pragma unroll
    for (int t = 0; t < 8; t++)
        sW4[tid + t*256] = __ldg(reinterpret_cast<const float4*>(Wft) + tid + t*256);
    __syncthreads();

    float4 a0 = make_float4(0.f,0.f,0.f,0.f), a1 = a0, a2 = a0, a3 = a0;   // px0..3 x outs og*4..+3

    const float* xb = x + (size_t)b * CIN * HWD + P0 + quad*4;
    const float4* sWp = sW4 + og;

    float4 L[4];
    #pragma unroll
    for (int i = 0; i < 4; i++)
        L[i] = *reinterpret_cast<const float4*>(xb + (size_t)i * HWD);

    for (int cb = 0; cb < CIN; cb += 4) {
        float4 M[4];
        if (cb + 4 < CIN) {
            #pragma unroll
            for (int i = 0; i < 4; i++)
                M[i] = *reinterpret_cast<const float4*>(xb + (size_t)(cb + 4 + i) * HWD);
        }
        #pragma unroll
        for (int i = 0; i < 4; i++) {
            float4 wv = sWp[(cb + i)*16];
            FMA4(a0, L[i].x, wv);
            FMA4(a1, L[i].y, wv);
            FMA4(a2, L[i].z, wv);
            FMA4(a3, L[i].w, wv);
        }
        #pragma unroll
        for (int i = 0; i < 4; i++) L[i] = M[i];
    }

    float* xtb = g_xt + (size_t)b * COUT * HWD + P0 + quad*4;
    const int ob = og*4;
    *reinterpret_cast<float4*>(xtb + (size_t)(ob+0) * HWD) = make_float4(a0.x, a1.x, a2.x, a3.x);
    *reinterpret_cast<float4*>(xtb + (size_t)(ob+1) * HWD) = make_float4(a0.y, a1.y, a2.y, a3.y);
    *reinterpret_cast<float4*>(xtb + (size_t)(ob+2) * HWD) = make_float4(a0.z, a1.z, a2.z, a3.z);
    *reinterpret_cast<float4*>(xtb + (size_t)(ob+3) * HWD) = make_float4(a0.w, a1.w, a2.w, a3.w);
}

// ---------------- kernel: per-bin partial sums + counts via shared atomics ----------------
__global__ void __launch_bounds__(256) k_sums(const int* __restrict__ idx) {
    __shared__ float sbm[64*33];
    const int tid = threadIdx.x;
    const int o = blockIdx.x, b = blockIdx.y, z = blockIdx.z;
    for (int i = tid; i < 64*33; i += 256) sbm[i] = 0.f;
    __syncthreads();
    const int col = tid & 31;
    const int4* ip4 = reinterpret_cast<const int4*>(idx + b*HWD);
    const int q0 = z*2048;
    if (o < COUT) {
        const float4* xt4 = reinterpret_cast<const float4*>(g_xt + (size_t)(b*COUT + o) * HWD);
        #pragma unroll
        for (int it = 0; it < 8; it++) {
            int q = q0 + it*256 + tid;
            float4 v = __ldg(xt4 + q);
            int4 kk = __ldg(ip4 + q);
            atomicAdd(&sbm[kk.x*33 + col], v.x);
            atomicAdd(&sbm[kk.y*33 + col], v.y);
            atomicAdd(&sbm[kk.z*33 + col], v.z);
            atomicAdd(&sbm[kk.w*33 + col], v.w);
        }
    } else {
        #pragma unroll
        for (int it = 0; it < 8; it++) {
            int q = q0 + it*256 + tid;
            int4 kk = __ldg(ip4 + q);
            atomicAdd(&sbm[kk.x*33 + col], 1.f);
            atomicAdd(&sbm[kk.y*33 + col], 1.f);
            atomicAdd(&sbm[kk.z*33 + col], 1.f);
            atomicAdd(&sbm[kk.w*33 + col], 1.f);
        }
    }
    __syncthreads();
    if (tid < 128) {
        int k = tid >> 1, h = tid & 1;
        float s = 0.f;
        const float* row = sbm + k*33 + h*16;
        #pragma unroll
        for (int m = 0; m < 16; m++) s += row[m];
        s += __shfl_xor_sync(0xffffffffu, s, 1);
        if (h == 0) {
            if (o < COUT) g_sumsp[((b*64 + k)*64 + o)*2 + z] = s;
            else          g_cntp[(b*64 + k)*2 + z] = s;
        }
    }
}

// ---------------- kernel: adjacency + adj@means per (b,i) ----------------
__global__ void __launch_bounds__(256) k_adj() {
    __shared__ float sMe[64*65];
    __shared__ float sA[64*64];
    __shared__ float adjrow[64];
    __shared__ float red[256];
    const int tid = threadIdx.x;
    const int b = blockIdx.x >> 6;
    const int i = blockIdx.x & 63;

    for (int t = tid; t < 64*64; t += 256) {
        int k = t >> 6, o = t & 63;
        float2 sp = *reinterpret_cast<const float2*>(g_sumsp + ((size_t)b*4096 + t)*2);
        float sum = sp.x + sp.y;
        float2 cp = *reinterpret_cast<const float2*>(g_cntp + (b*64 + k)*2);
        float cnt = cp.x + cp.y;
        float den = cnt + (cnt == 0.f ? 1.f : 0.f);
        sMe[k*65 + o] = sum / den;
        sA[t] = g_A[t];
    }
    __syncthreads();

    const int j = tid & 63, s = tid >> 6;
    float dreg[64];
    #pragma unroll
    for (int d = 0; d < 64; d++) dreg[d] = sMe[i*65 + d] - sMe[j*65 + d];
    float q = 0.f;
    for (int c = s*16; c < s*16 + 16; c++) {
        float w = 0.f;
        const float4* ar = reinterpret_cast<const float4*>(sA + c*64);
        #pragma unroll
        for (int d4 = 0; d4 < 16; d4++) {
            float4 aa = ar[d4];
            w += aa.x*dreg[4*d4] + aa.y*dreg[4*d4+1] + aa.z*dreg[4*d4+2] + aa.w*dreg[4*d4+3];
        }
        q += dreg[c] * w;
    }
    red[tid] = q;
    __syncthreads();
    if (tid < 64) {
        float qt = red[tid] + red[64 + tid] + red[128 + tid] + red[192 + tid];
        float dist = (tid == i) ? 1e-6f : sqrtf(fmaxf(qt, 1e-12f));
        adjrow[tid] = expf(-dist);
    }
    __syncthreads();
    const int o = tid & 63;
    float part = 0.f;
    for (int jj = s*16; jj < s*16 + 16; jj++) part += adjrow[jj] * sMe[jj*65 + o];
    red[tid] = part;
    __syncthreads();
    if (tid < 64)
        g_adjmT[b*4096 + tid*64 + i] = red[tid] + red[64 + tid] + red[128 + tid] + red[192 + tid];
}

// ---------------- kernel: BN partial statistics ----------------
__global__ void __launch_bounds__(256) k_stats(const int* __restrict__ idx) {
    __shared__ float sAm[64];
    const int tid = threadIdx.x;
    const int cx = blockIdx.x, o = blockIdx.y, b = blockIdx.z;
    if (tid < 64) sAm[tid] = g_adjmT[b*4096 + o*64 + tid];
    __syncthreads();
    const float4* xt4 = reinterpret_cast<const float4*>(g_xt + (size_t)(b*COUT + o) * HWD);
    const int4*   ip4 = reinterpret_cast<const int4*>(idx + b*HWD);
    int q0 = cx * 512 + tid;
    float s = 0.f, sq = 0.f;
    #pragma unroll
    for (int it = 0; it < 2; it++) {
        int q = q0 + it*256;
        float4 v = __ldg(xt4 + q);
        int4 kk = __ldg(ip4 + q);
        float f0 = fmaxf(v.x + sAm[kk.x], 0.f);
        float f1 = fmaxf(v.y + sAm[kk.y], 0.f);
        float f2 = fmaxf(v.z + sAm[kk.z], 0.f);
        float f3 = fmaxf(v.w + sAm[kk.w], 0.f);
        s  += f0 + f1 + f2 + f3;
        sq += f0*f0 + f1*f1 + f2*f2 + f3*f3;
    }
    #pragma unroll
    for (int off = 16; off; off >>= 1) {
        s  += __shfl_down_sync(0xffffffffu, s, off);
        sq += __shfl_down_sync(0xffffffffu, sq, off);
    }
    __shared__ float rs[8], rq[8];
    if ((tid & 31) == 0) { rs[tid >> 5] = s; rq[tid >> 5] = sq; }
    __syncthreads();
    if (tid == 0) {
        float S = 0.f, Q = 0.f;
        #pragma unroll
        for (int w = 0; w < 8; w++) { S += rs[w]; Q += rq[w]; }
        g_psum[(b*8 + cx)*COUT + o] = S;
        g_psq [(b*8 + cx)*COUT + o] = Q;
    }
}

// ---------------- kernel: normalize + write output ----------------
__global__ void __launch_bounds__(256) k_out(const int* __restrict__ idx,
                                             const float* __restrict__ gamma,
                                             const float* __restrict__ beta,
                                             float* __restrict__ out) {
    __shared__ float sAm[64];
    __shared__ float sc, shf;
    const int tid = threadIdx.x;
    const int cx = blockIdx.x, o = blockIdx.y, b = blockIdx.z;
    if (tid < 64) sAm[tid] = g_adjmT[b*4096 + o*64 + tid];
    if (tid == 0) {
        float S = 0.f, Q = 0.f;
        #pragma unroll
        for (int i = 0; i < 16; i++) { S += g_psum[i*COUT + o]; Q += g_psq[i*COUT + o]; }
        const float invN = 1.0f / (float)NPIX;
        float mean = S * invN;
        float var  = Q * invN - mean * mean;
        float inv  = 1.0f / sqrtf(var + 1e-5f);
        float g = __ldg(gamma + o), be = __ldg(beta + o);
        sc  = g * inv;
        shf = be - mean * g * inv;
    }
    __syncthreads();
    const float4* xt4 = reinterpret_cast<const float4*>(g_xt + (size_t)(b*COUT + o) * HWD);
    const int4*   ip4 = reinterpret_cast<const int4*>(idx + b*HWD);
    float4* o4 = reinterpret_cast<float4*>(out + (size_t)(b*COUT + o) * HWD);
    int q0 = cx * 512 + tid;
    float lsc = sc, lsh = shf;
    #pragma unroll
    for (int it = 0; it < 2; it++) {
        int q = q0 + it*256;
        float4 v = __ldg(xt4 + q);
        int4 kk = __ldg(ip4 + q);
        float4 r;
        r.x = fmaxf(v.x + sAm[kk.x], 0.f) * lsc + lsh;
        r.y = fmaxf(v.y + sAm[kk.y], 0.f) * lsc + lsh;
        r.z = fmaxf(v.z + sAm[kk.z], 0.f) * lsc + lsh;
        r.w = fmaxf(v.w + sAm[kk.w], 0.f) * lsc + lsh;
        o4[q] = r;
    }
}

// ---------------- launch ----------------
extern "C" void kernel_launch(void* const* d_in, const int* in_sizes, int n_in,
                              void* d_out, int out_size) {
    const float* x     = (const float*)d_in[0];
    const int*   idx   = (const int*)  d_in[1];
    const float* Wft   = (const float*)d_in[2];
    const float* Wm    = (const float*)d_in[3];
    const float* gamma = (const float*)d_in[4];
    const float* beta  = (const float*)d_in[5];
    float* out = (float*)d_out;

    k_gemm<<<NGB + 1, 256>>>(x, Wft, Wm);
    k_sums<<<dim3(COUT + 1, BB, 2), 256>>>(idx);
    k_adj<<<BB*KK, 256>>>();
    k_stats<<<dim3(8, COUT, BB), 256>>>(idx);
    k_out<<<dim3(8, COUT, BB), 256>>>(idx, gamma, beta, out);
}